// round 12
// baseline (speedup 1.0000x reference)
#include <cuda_runtime.h>
#include <cstdint>

#define BB 4
#define NN 2048
#define FIN 128
#define HH 4
#define DKK 32
#define LOG2E 1.4426950408889634f

// Scratch (no cudaMalloc allowed)
// g_hB: tf32 H^T in MMA-B fragment order:
//   slot = (((bh*16 + g)*16 + kc)*4 + nt)*64 + d_loc*8 + 2*(j8&3) + (j8>>2)
__device__ float g_hB[BB*HH*16*16*4*64];
__device__ float g_el[BB*HH*NN];           // pre-scaled by LOG2E
__device__ float g_er[BB*HH*NN];           // pre-scaled by LOG2E
// Ballot-direct bitmask: word (b, g=j>>7, s=j&3), bit (j>>2)&31, indexed [i]
__device__ unsigned g_bits[BB*64*NN];

// ---------------------------------------------------------------------------
// Kernel A: pack adj -> ballot-direct bitmask. Warp = (b, g, 32-row chunk);
// int4 row loads (512B/warp/row, MLP=32) + 4 ballots -> 4 coalesced words.
// ---------------------------------------------------------------------------
__global__ __launch_bounds__(256) void pack_adj_k(const int* __restrict__ adj) {
    int t = threadIdx.x, w = t >> 5, lane = t & 31;
    int task = blockIdx.x * 8 + w;              // 4096 tasks
    int ic = task & 63;
    int g  = (task >> 6) & 15;
    int b  = task >> 10;
    int i0 = ic * 32;
    const int4* src = (const int4*)(adj + ((long long)(b * NN + i0)) * NN + g * 128) + lane;
    unsigned m0 = 0, m1 = 0, m2 = 0, m3 = 0;
#pragma unroll 8
    for (int r = 0; r < 32; r++) {
        int4 v = src[(long long)r * (NN / 4)];
        unsigned b0 = __ballot_sync(0xffffffffu, v.x != 0);
        unsigned b1 = __ballot_sync(0xffffffffu, v.y != 0);
        unsigned b2 = __ballot_sync(0xffffffffu, v.z != 0);
        unsigned b3 = __ballot_sync(0xffffffffu, v.w != 0);
        if (lane == r) { m0 = b0; m1 = b1; m2 = b2; m3 = b3; }
    }
    unsigned* dst = g_bits + ((long long)(b * 16 + g) * 4) * NN + i0 + lane;
    dst[0]      = m0;
    dst[NN]     = m1;
    dst[2 * NN] = m2;
    dst[3 * NN] = m3;
}

// ---------------------------------------------------------------------------
// Kernel B: h = x @ W. Fragment-ordered tf32 g_hB + fused el/er.
// ---------------------------------------------------------------------------
__global__ __launch_bounds__(256) void compute_h_k(const float* __restrict__ x,
                                                   const float* __restrict__ W,
                                                   const float* __restrict__ a) {
    __shared__ float xs[32][FIN];
    __shared__ float sT[128][33];
    int t = threadIdx.x, lane = t & 31;
    int row0 = blockIdx.x * 32;
    for (int idx = t; idx < 32 * FIN; idx += 256)
        xs[idx >> 7][idx & 127] = x[(long long)row0 * FIN + idx];
    __syncthreads();

    int c  = t & 127;
    int hh = c >> 5;
    int d  = c & 31;
    int rb = (t >> 7) * 16;

    float acc[16];
#pragma unroll
    for (int r = 0; r < 16; r++) acc[r] = 0.f;

    const float* Wc = W + hh * FIN * DKK + d;
    for (int i0 = 0; i0 < FIN; i0 += 4) {
        float w0 = __ldg(Wc + i0 * DKK);
        float w1 = __ldg(Wc + (i0 + 1) * DKK);
        float w2 = __ldg(Wc + (i0 + 2) * DKK);
        float w3 = __ldg(Wc + (i0 + 3) * DKK);
#pragma unroll
        for (int r = 0; r < 16; r++) {
            float4 xv = *(const float4*)&xs[rb + r][i0];
            acc[r] = fmaf(xv.x, w0, acc[r]);
            acc[r] = fmaf(xv.y, w1, acc[r]);
            acc[r] = fmaf(xv.z, w2, acc[r]);
            acc[r] = fmaf(xv.w, w3, acc[r]);
        }
    }

    int b  = row0 / NN;
    int n0 = row0 % NN;
    int bh = b * HH + hh;

    float al = __ldg(a + hh * 2 * DKK + lane);
    float ar = __ldg(a + hh * 2 * DKK + DKK + lane);
#pragma unroll
    for (int r = 0; r < 16; r++) {
        float el = acc[r] * al, er = acc[r] * ar;
#pragma unroll
        for (int o = 16; o > 0; o >>= 1) {
            el += __shfl_xor_sync(0xffffffffu, el, o);
            er += __shfl_xor_sync(0xffffffffu, er, o);
        }
        if (lane == 0) {
            g_el[(long long)bh * NN + n0 + rb + r] = el * LOG2E;
            g_er[(long long)bh * NN + n0 + rb + r] = er * LOG2E;
        }
    }

#pragma unroll
    for (int r = 0; r < 16; r++) {
        unsigned tv;
        asm("cvt.rna.tf32.f32 %0, %1;" : "=r"(tv) : "f"(acc[r]));
        sT[c][rb + r] = __uint_as_float(tv);
    }
    __syncthreads();

    // g_hB fragment order; interleaved j: positions [4*j4..4*j4+3] hold
    // j-values {2*j4, 2*j4+4, 2*j4+1, 2*j4+5}. sT rows odd-padded -> scalar.
    int jt  = n0 >> 7;
    int kc0 = (n0 >> 3) & 15;
#pragma unroll
    for (int k = 0; k < 4; k++) {
        int q = t + k * 256;
        int j4    = q & 1;
        int d_loc = (q >> 1) & 7;
        int nt    = (q >> 4) & 3;
        int kcl   = (q >> 6) & 3;
        int h2    = q >> 8;
        int dd   = nt * 8 + d_loc;
        int base = kcl * 8;
        int row  = h2 * 32 + dd;
        float4 v = make_float4(sT[row][base + 2 * j4],
                               sT[row][base + 2 * j4 + 4],
                               sT[row][base + 2 * j4 + 1],
                               sT[row][base + 2 * j4 + 5]);
        long long off = ((((long long)((b * HH + h2) * 16 + jt) * 16 + (kc0 + kcl)) * 4 + nt) * 64)
                        + d_loc * 8 + j4 * 4;
        *(float4*)(g_hB + off) = v;
    }
}

// ---------------------------------------------------------------------------
// Kernel C: fused masked-softmax + aggregate via mma.sync tf32 m16n8k8.
// 128-thread blocks, i-tile 64: warp = 16 i-rows (one m16 tile) x FULL j.
// No cross-warp reduction; high occupancy (8 blocks/SM) hides stalls.
// ---------------------------------------------------------------------------
__device__ __forceinline__ unsigned p_gen(float el, float er, unsigned wrd, int pos) {
    float e = el + er;
    float l = fmaxf(e, 0.2f * e);
    float pe;
    asm("ex2.approx.f32 %0, %1;" : "=f"(pe) : "f"(l));
    unsigned bit;
    asm("bfe.u32 %0, %1, %2, 1;" : "=r"(bit) : "r"(wrd), "r"(pos));
    float p = bit ? pe : 0.f;
    return __float_as_uint(p);
}

#define MMA4(accp, A0, A1, A2, A3, B0, B1)                                    \
    asm("mma.sync.aligned.m16n8k8.row.col.f32.tf32.tf32.f32 "                 \
        "{%0,%1,%2,%3}, {%4,%5,%6,%7}, {%8,%9}, {%0,%1,%2,%3};"               \
        : "+f"((accp)[0]), "+f"((accp)[1]), "+f"((accp)[2]), "+f"((accp)[3])  \
        : "r"(A0), "r"(A1), "r"(A2), "r"(A3), "r"(B0), "r"(B1))

__global__ __launch_bounds__(128, 8) void gat_attn_mma_k(float* __restrict__ out) {
    __shared__ float er_s[NN];     // 8 KB
    __shared__ float Bf[4096];     // 16 KB: one 128-j fragment tile

    int t = threadIdx.x, w = t >> 5, lane = t & 31;
    int bid = blockIdx.x;
    int it = bid & 31;                       // 32 i-tiles of 64
    int hh = (bid >> 5) & 3;
    int b  = bid >> 7;
    int bh = b * HH + hh;
    int iw = it * 64 + w * 16;               // warp's 16 i-rows
    int r  = lane >> 2;
    int c0 = lane & 3;

    {
        float4* edst = (float4*)er_s;
        const float4* esrc = (const float4*)(g_er + (long long)bh * NN);
#pragma unroll
        for (int k = 0; k < 4; k++) edst[t + k * 128] = esrc[t + k * 128];
    }
    float el0 = g_el[(long long)bh * NN + iw + r];
    float el1 = g_el[(long long)bh * NN + iw + r + 8];

    float acc[4][4];
    float accS[4];
#pragma unroll
    for (int nt = 0; nt < 4; nt++)
#pragma unroll
        for (int q = 0; q < 4; q++) acc[nt][q] = 0.f;
#pragma unroll
    for (int q = 0; q < 4; q++) accS[q] = 0.f;

    const float* hBb = g_hB + (long long)bh * 65536;
    const unsigned* bitb = g_bits + (long long)b * 64 * NN;
    const unsigned ONE = 0x3F800000u;

    for (int mt = 0; mt < 16; mt++) {
        __syncthreads();                     // previous tile consumed
        {
            const float4* src = (const float4*)(hBb + mt * 4096);
            float4* dst = (float4*)Bf;
#pragma unroll
            for (int k = 0; k < 8; k++) dst[t + k * 128] = src[t + k * 128];
        }
        // bit words for this 128-j tile (ballot-direct: g=mt, s=c0)
        const unsigned* bw = bitb + (long long)(mt * 4 + c0) * NN + iw + r;
        unsigned w0a = bw[0], w0b = bw[8];
        __syncthreads();

#pragma unroll 4
        for (int kc = 0; kc < 16; kc++) {
            int eoff = mt * 128 + kc * 8 + c0;
            float e0 = er_s[eoff];
            float e4 = er_s[eoff + 4];
            int p0 = 2 * kc, p1 = 2 * kc + 1;

            unsigned a0 = p_gen(el0, e0, w0a, p0);
            unsigned a1 = p_gen(el1, e0, w0b, p0);
            unsigned a2 = p_gen(el0, e4, w0a, p1);
            unsigned a3 = p_gen(el1, e4, w0b, p1);

            const float2* bp = (const float2*)(Bf + kc * 256) + lane;
#pragma unroll
            for (int nt = 0; nt < 4; nt++) {
                float2 bv = bp[nt * 32];
                MMA4(acc[nt], a0, a1, a2, a3,
                     __float_as_uint(bv.x), __float_as_uint(bv.y));
            }
            MMA4(accS, a0, a1, a2, a3, ONE, ONE);   // row sums
        }
    }

    // ---- epilogue: no reduction needed (warp owned full j) ----
    float invl = 1.f / accS[0];
    float invh = 1.f / accS[2];
    float* ob = out + ((long long)bh * NN + iw + r) * DKK;
#pragma unroll
    for (int nt = 0; nt < 4; nt++) {
        int col = nt * 8 + 2 * c0;
        float2 v0 = make_float2(acc[nt][0] * invl, acc[nt][1] * invl);
        float2 v1 = make_float2(acc[nt][2] * invh, acc[nt][3] * invh);
        *(float2*)(ob + col) = v0;
        *(float2*)(ob + 8 * DKK + col) = v1;
    }
}

// ---------------------------------------------------------------------------
extern "C" void kernel_launch(void* const* d_in, const int* in_sizes, int n_in,
                              void* d_out, int out_size) {
    const float* x   = (const float*)d_in[0];
    const int*   adj = (const int*)d_in[1];
    const float* W   = (const float*)d_in[2];
    const float* a   = (const float*)d_in[3];
    float* out = (float*)d_out;

    pack_adj_k<<<512, 256>>>(adj);
    compute_h_k<<<(BB * NN) / 32, 256>>>(x, W, a);
    gat_attn_mma_k<<<BB * HH * 32, 128>>>(out);
}

// round 13
// speedup vs baseline: 1.0364x; 1.0364x over previous
#include <cuda_runtime.h>
#include <cstdint>

#define BB 4
#define NN 2048
#define FIN 128
#define HH 4
#define DKK 32
#define LOG2E 1.4426950408889634f

// Scratch (no cudaMalloc allowed)
__device__ float g_hB[BB*HH*16*16*4*64];   // tf32 H^T, MMA-B fragment order
__device__ float g_el[BB*HH*NN];           // pre-scaled by LOG2E
__device__ float g_er[BB*HH*NN];           // pre-scaled by LOG2E
__device__ unsigned g_bits[BB*64*NN];      // ballot-direct bitmask
__device__ float g_pacc[2*16*NN*DKK];      // j-split partial acc  (16.8 MB)
__device__ float g_psum[2*16*NN];          // j-split partial row sums

// ---------------------------------------------------------------------------
// Kernel A: pack adj -> ballot-direct bitmask (word (b,g,s), bit (j>>2)&31).
// ---------------------------------------------------------------------------
__global__ __launch_bounds__(256) void pack_adj_k(const int* __restrict__ adj) {
    int t = threadIdx.x, w = t >> 5, lane = t & 31;
    int task = blockIdx.x * 8 + w;
    int ic = task & 63;
    int g  = (task >> 6) & 15;
    int b  = task >> 10;
    int i0 = ic * 32;
    const int4* src = (const int4*)(adj + ((long long)(b * NN + i0)) * NN + g * 128) + lane;
    unsigned m0 = 0, m1 = 0, m2 = 0, m3 = 0;
#pragma unroll 8
    for (int r = 0; r < 32; r++) {
        int4 v = src[(long long)r * (NN / 4)];
        unsigned b0 = __ballot_sync(0xffffffffu, v.x != 0);
        unsigned b1 = __ballot_sync(0xffffffffu, v.y != 0);
        unsigned b2 = __ballot_sync(0xffffffffu, v.z != 0);
        unsigned b3 = __ballot_sync(0xffffffffu, v.w != 0);
        if (lane == r) { m0 = b0; m1 = b1; m2 = b2; m3 = b3; }
    }
    unsigned* dst = g_bits + ((long long)(b * 16 + g) * 4) * NN + i0 + lane;
    dst[0]      = m0;
    dst[NN]     = m1;
    dst[2 * NN] = m2;
    dst[3 * NN] = m3;
}

// ---------------------------------------------------------------------------
// Kernel B: h = x @ W. Fragment-ordered tf32 g_hB + fused el/er.
// ---------------------------------------------------------------------------
__global__ __launch_bounds__(256) void compute_h_k(const float* __restrict__ x,
                                                   const float* __restrict__ W,
                                                   const float* __restrict__ a) {
    __shared__ float xs[32][FIN];
    __shared__ float sT[128][33];
    int t = threadIdx.x, lane = t & 31;
    int row0 = blockIdx.x * 32;
    for (int idx = t; idx < 32 * FIN; idx += 256)
        xs[idx >> 7][idx & 127] = x[(long long)row0 * FIN + idx];
    __syncthreads();

    int c  = t & 127;
    int hh = c >> 5;
    int d  = c & 31;
    int rb = (t >> 7) * 16;

    float acc[16];
#pragma unroll
    for (int r = 0; r < 16; r++) acc[r] = 0.f;

    const float* Wc = W + hh * FIN * DKK + d;
    for (int i0 = 0; i0 < FIN; i0 += 4) {
        float w0 = __ldg(Wc + i0 * DKK);
        float w1 = __ldg(Wc + (i0 + 1) * DKK);
        float w2 = __ldg(Wc + (i0 + 2) * DKK);
        float w3 = __ldg(Wc + (i0 + 3) * DKK);
#pragma unroll
        for (int r = 0; r < 16; r++) {
            float4 xv = *(const float4*)&xs[rb + r][i0];
            acc[r] = fmaf(xv.x, w0, acc[r]);
            acc[r] = fmaf(xv.y, w1, acc[r]);
            acc[r] = fmaf(xv.z, w2, acc[r]);
            acc[r] = fmaf(xv.w, w3, acc[r]);
        }
    }

    int b  = row0 / NN;
    int n0 = row0 % NN;
    int bh = b * HH + hh;

    float al = __ldg(a + hh * 2 * DKK + lane);
    float ar = __ldg(a + hh * 2 * DKK + DKK + lane);
#pragma unroll
    for (int r = 0; r < 16; r++) {
        float el = acc[r] * al, er = acc[r] * ar;
#pragma unroll
        for (int o = 16; o > 0; o >>= 1) {
            el += __shfl_xor_sync(0xffffffffu, el, o);
            er += __shfl_xor_sync(0xffffffffu, er, o);
        }
        if (lane == 0) {
            g_el[(long long)bh * NN + n0 + rb + r] = el * LOG2E;
            g_er[(long long)bh * NN + n0 + rb + r] = er * LOG2E;
        }
    }

#pragma unroll
    for (int r = 0; r < 16; r++) {
        unsigned tv;
        asm("cvt.rna.tf32.f32 %0, %1;" : "=r"(tv) : "f"(acc[r]));
        sT[c][rb + r] = __uint_as_float(tv);
    }
    __syncthreads();

    int jt  = n0 >> 7;
    int kc0 = (n0 >> 3) & 15;
#pragma unroll
    for (int k = 0; k < 4; k++) {
        int q = t + k * 256;
        int j4    = q & 1;
        int d_loc = (q >> 1) & 7;
        int nt    = (q >> 4) & 3;
        int kcl   = (q >> 6) & 3;
        int h2    = q >> 8;
        int dd   = nt * 8 + d_loc;
        int base = kcl * 8;
        int row  = h2 * 32 + dd;
        float4 v = make_float4(sT[row][base + 2 * j4],
                               sT[row][base + 2 * j4 + 4],
                               sT[row][base + 2 * j4 + 1],
                               sT[row][base + 2 * j4 + 5]);
        long long off = ((((long long)((b * HH + h2) * 16 + jt) * 16 + (kc0 + kcl)) * 4 + nt) * 64)
                        + d_loc * 8 + j4 * 4;
        *(float4*)(g_hB + off) = v;
    }
}

// ---------------------------------------------------------------------------
// Kernel C: masked-softmax + aggregate, j-split S=2 across grid.
// Block = (s, it, hh, b): i-tile 128, j-range 1024. Warp = 32 i (2 m16
// tiles sharing B) x block-j-half. Writes UNNORMALIZED partials.
// ---------------------------------------------------------------------------
__device__ __forceinline__ unsigned p_gen(float el, float er, unsigned wrd, int pos) {
    float e = el + er;
    float l = fmaxf(e, 0.2f * e);
    float pe;
    asm("ex2.approx.f32 %0, %1;" : "=f"(pe) : "f"(l));
    unsigned bit;
    asm("bfe.u32 %0, %1, %2, 1;" : "=r"(bit) : "r"(wrd), "r"(pos));
    float p = bit ? pe : 0.f;
    return __float_as_uint(p);
}

#define MMA4(accp, A0, A1, A2, A3, B0, B1)                                    \
    asm("mma.sync.aligned.m16n8k8.row.col.f32.tf32.tf32.f32 "                 \
        "{%0,%1,%2,%3}, {%4,%5,%6,%7}, {%8,%9}, {%0,%1,%2,%3};"               \
        : "+f"((accp)[0]), "+f"((accp)[1]), "+f"((accp)[2]), "+f"((accp)[3])  \
        : "r"(A0), "r"(A1), "r"(A2), "r"(A3), "r"(B0), "r"(B1))

__global__ __launch_bounds__(256, 3) void gat_attn_mma_k() {
    __shared__ float er_s[1024];   // 4 KB: block's j-range
    __shared__ float Bf[8192];     // 32 KB; reused as reduction buffer

    int t = threadIdx.x, w = t >> 5, lane = t & 31;
    int bid = blockIdx.x;
    int s  = bid & 1;
    int it = (bid >> 1) & 15;
    int hh = (bid >> 5) & 3;
    int b  = bid >> 7;
    int bh = b * HH + hh;

    int half = w >> 2;
    int iw   = it * 128 + (w & 3) * 32;
    int r    = lane >> 2;
    int c0   = lane & 3;

    {
        float4* edst = (float4*)er_s;
        const float4* esrc = (const float4*)(g_er + (long long)bh * NN + s * 1024);
        edst[t] = esrc[t];
    }
    const float* elp = g_el + (long long)bh * NN + iw + r;
    float el0 = elp[0], el1 = elp[8], el2 = elp[16], el3 = elp[24];

    float acc[2][4][4];
    float accS[2][4];
#pragma unroll
    for (int m = 0; m < 2; m++) {
#pragma unroll
        for (int nt = 0; nt < 4; nt++)
#pragma unroll
            for (int q = 0; q < 4; q++) acc[m][nt][q] = 0.f;
#pragma unroll
        for (int q = 0; q < 4; q++) accS[m][q] = 0.f;
    }

    const float* hBb = g_hB + (long long)bh * 65536;
    const unsigned* bitb = g_bits + (long long)b * 64 * NN;
    const unsigned ONE = 0x3F800000u;

    for (int mtl = 0; mtl < 4; mtl++) {
        __syncthreads();
        {
            const float4* s0 = (const float4*)(hBb + (s * 8 + mtl) * 4096);
            const float4* s1 = (const float4*)(hBb + (s * 8 + 4 + mtl) * 4096);
            float4* dst = (float4*)Bf;
#pragma unroll
            for (int k = 0; k < 4; k++) {
                dst[t + k * 256]        = s0[t + k * 256];
                dst[1024 + t + k * 256] = s1[t + k * 256];
            }
        }
        int gm = s * 8 + half * 4 + mtl;
        const unsigned* bw = bitb + (long long)(gm * 4 + c0) * NN + iw + r;
        unsigned w0a = bw[0], w0b = bw[8], w1a = bw[16], w1b = bw[24];
        __syncthreads();

#pragma unroll 4
        for (int kc = 0; kc < 16; kc++) {
            int eoff = half * 512 + mtl * 128 + kc * 8 + c0;
            float e0 = er_s[eoff];
            float e4 = er_s[eoff + 4];
            int p0 = 2 * kc, p1 = 2 * kc + 1;

            unsigned a00 = p_gen(el0, e0, w0a, p0);
            unsigned a01 = p_gen(el1, e0, w0b, p0);
            unsigned a02 = p_gen(el0, e4, w0a, p1);
            unsigned a03 = p_gen(el1, e4, w0b, p1);
            unsigned a10 = p_gen(el2, e0, w1a, p0);
            unsigned a11 = p_gen(el3, e0, w1b, p0);
            unsigned a12 = p_gen(el2, e4, w1a, p1);
            unsigned a13 = p_gen(el3, e4, w1b, p1);

            const float2* bp = (const float2*)(Bf + half * 4096 + kc * 256) + lane;
#pragma unroll
            for (int nt = 0; nt < 4; nt++) {
                float2 bv = bp[nt * 32];
                unsigned b0 = __float_as_uint(bv.x);
                unsigned b1 = __float_as_uint(bv.y);
                MMA4(acc[0][nt], a00, a01, a02, a03, b0, b1);
                MMA4(acc[1][nt], a10, a11, a12, a13, b0, b1);
            }
            MMA4(accS[0], a00, a01, a02, a03, ONE, ONE);
            MMA4(accS[1], a10, a11, a12, a13, ONE, ONE);
        }
    }

    // ---- combine the two block-j-halves ----
    __syncthreads();
    float* red = Bf;
    if (w >= 4) {
        int base = ((w - 4) * 32 + lane) * 36;
#pragma unroll
        for (int m = 0; m < 2; m++) {
#pragma unroll
            for (int nt = 0; nt < 4; nt++)
#pragma unroll
                for (int q = 0; q < 4; q++)
                    red[base + m * 16 + nt * 4 + q] = acc[m][nt][q];
            red[base + 32 + m * 2]     = accS[m][0];
            red[base + 32 + m * 2 + 1] = accS[m][2];
        }
    }
    __syncthreads();
    if (w < 4) {
        int base = (w * 32 + lane) * 36;
        int sb = s * 16 + bh;
#pragma unroll
        for (int m = 0; m < 2; m++) {
#pragma unroll
            for (int nt = 0; nt < 4; nt++)
#pragma unroll
                for (int q = 0; q < 4; q++)
                    acc[m][nt][q] += red[base + m * 16 + nt * 4 + q];
            float sl = accS[m][0] + red[base + 32 + m * 2];
            float sh = accS[m][2] + red[base + 32 + m * 2 + 1];
            int gi = iw + m * 16 + r;
            if (c0 == 0) {
                g_psum[(long long)sb * NN + gi]     = sl;
                g_psum[(long long)sb * NN + gi + 8] = sh;
            }
            float* pb = g_pacc + ((long long)sb * NN + gi) * DKK;
#pragma unroll
            for (int nt = 0; nt < 4; nt++) {
                int col = nt * 8 + 2 * c0;
                *(float2*)(pb + col) = make_float2(acc[m][nt][0], acc[m][nt][1]);
                *(float2*)(pb + 8 * DKK + col) = make_float2(acc[m][nt][2], acc[m][nt][3]);
            }
        }
    }
}

// ---------------------------------------------------------------------------
// Kernel D: reduce the 2 j-split partials + normalize + write out.
// ---------------------------------------------------------------------------
__global__ __launch_bounds__(256) void reduce_k(float* __restrict__ out) {
    int q = blockIdx.x * 256 + threadIdx.x;   // 131072 threads
    int row  = q >> 2;                        // (bh, i): 32768 rows
    int dseg = (q & 3) * 8;
    int bh = row >> 11;
    int i  = row & 2047;
    float s0 = g_psum[(long long)bh * NN + i];
    float s1 = g_psum[(long long)(16 + bh) * NN + i];
    float inv = 1.f / (s0 + s1);
    const float4* p0 = (const float4*)(g_pacc + ((long long)bh * NN + i) * DKK + dseg);
    const float4* p1 = (const float4*)(g_pacc + ((long long)(16 + bh) * NN + i) * DKK + dseg);
    float4* ob = (float4*)(out + ((long long)bh * NN + i) * DKK + dseg);
#pragma unroll
    for (int k = 0; k < 2; k++) {
        float4 u = p0[k], v = p1[k];
        ob[k] = make_float4((u.x + v.x) * inv, (u.y + v.y) * inv,
                            (u.z + v.z) * inv, (u.w + v.w) * inv);
    }
}

// ---------------------------------------------------------------------------
extern "C" void kernel_launch(void* const* d_in, const int* in_sizes, int n_in,
                              void* d_out, int out_size) {
    const float* x   = (const float*)d_in[0];
    const int*   adj = (const int*)d_in[1];
    const float* W   = (const float*)d_in[2];
    const float* a   = (const float*)d_in[3];
    float* out = (float*)d_out;

    pack_adj_k<<<512, 256>>>(adj);
    compute_h_k<<<(BB * NN) / 32, 256>>>(x, W, a);
    gat_attn_mma_k<<<BB * HH * 16 * 2, 256>>>();
    reduce_k<<<512, 256>>>(out);
}

// round 14
// speedup vs baseline: 1.0679x; 1.0304x over previous
#include <cuda_runtime.h>
#include <cstdint>

#define BB 4
#define NN 2048
#define FIN 128
#define HH 4
#define DKK 32
#define LOG2E 1.4426950408889634f

// Scratch (no cudaMalloc allowed)
__device__ float g_hB[BB*HH*16*16*4*64];   // tf32 H^T, MMA-B fragment order
__device__ float g_el[BB*HH*NN];           // pre-scaled by LOG2E
__device__ float g_er[BB*HH*NN];           // pre-scaled by LOG2E
__device__ unsigned g_bits[BB*64*NN];      // ballot-direct bitmask
__device__ float g_pacc[2*16*NN*DKK];      // j-split partial acc
__device__ float g_psum[2*16*NN];          // j-split partial row sums

// ---------------------------------------------------------------------------
// Kernel A: pack adj -> ballot-direct bitmask (word (b,g,s), bit (j>>2)&31).
// ---------------------------------------------------------------------------
__global__ __launch_bounds__(256) void pack_adj_k(const int* __restrict__ adj) {
    int t = threadIdx.x, w = t >> 5, lane = t & 31;
    int task = blockIdx.x * 8 + w;
    int ic = task & 63;
    int g  = (task >> 6) & 15;
    int b  = task >> 10;
    int i0 = ic * 32;
    const int4* src = (const int4*)(adj + ((long long)(b * NN + i0)) * NN + g * 128) + lane;
    unsigned m0 = 0, m1 = 0, m2 = 0, m3 = 0;
#pragma unroll 8
    for (int r = 0; r < 32; r++) {
        int4 v = src[(long long)r * (NN / 4)];
        unsigned b0 = __ballot_sync(0xffffffffu, v.x != 0);
        unsigned b1 = __ballot_sync(0xffffffffu, v.y != 0);
        unsigned b2 = __ballot_sync(0xffffffffu, v.z != 0);
        unsigned b3 = __ballot_sync(0xffffffffu, v.w != 0);
        if (lane == r) { m0 = b0; m1 = b1; m2 = b2; m3 = b3; }
    }
    unsigned* dst = g_bits + ((long long)(b * 16 + g) * 4) * NN + i0 + lane;
    dst[0]      = m0;
    dst[NN]     = m1;
    dst[2 * NN] = m2;
    dst[3 * NN] = m3;
}

// ---------------------------------------------------------------------------
// Kernel B: h = x @ W. Fragment-ordered tf32 g_hB + fused el/er.
// ---------------------------------------------------------------------------
__global__ __launch_bounds__(256) void compute_h_k(const float* __restrict__ x,
                                                   const float* __restrict__ W,
                                                   const float* __restrict__ a) {
    __shared__ float xs[32][FIN];
    __shared__ float sT[128][33];
    int t = threadIdx.x, lane = t & 31;
    int row0 = blockIdx.x * 32;
    for (int idx = t; idx < 32 * FIN; idx += 256)
        xs[idx >> 7][idx & 127] = x[(long long)row0 * FIN + idx];
    __syncthreads();

    int c  = t & 127;
    int hh = c >> 5;
    int d  = c & 31;
    int rb = (t >> 7) * 16;

    float acc[16];
#pragma unroll
    for (int r = 0; r < 16; r++) acc[r] = 0.f;

    const float* Wc = W + hh * FIN * DKK + d;
    for (int i0 = 0; i0 < FIN; i0 += 4) {
        float w0 = __ldg(Wc + i0 * DKK);
        float w1 = __ldg(Wc + (i0 + 1) * DKK);
        float w2 = __ldg(Wc + (i0 + 2) * DKK);
        float w3 = __ldg(Wc + (i0 + 3) * DKK);
#pragma unroll
        for (int r = 0; r < 16; r++) {
            float4 xv = *(const float4*)&xs[rb + r][i0];
            acc[r] = fmaf(xv.x, w0, acc[r]);
            acc[r] = fmaf(xv.y, w1, acc[r]);
            acc[r] = fmaf(xv.z, w2, acc[r]);
            acc[r] = fmaf(xv.w, w3, acc[r]);
        }
    }

    int b  = row0 / NN;
    int n0 = row0 % NN;
    int bh = b * HH + hh;

    float al = __ldg(a + hh * 2 * DKK + lane);
    float ar = __ldg(a + hh * 2 * DKK + DKK + lane);
#pragma unroll
    for (int r = 0; r < 16; r++) {
        float el = acc[r] * al, er = acc[r] * ar;
#pragma unroll
        for (int o = 16; o > 0; o >>= 1) {
            el += __shfl_xor_sync(0xffffffffu, el, o);
            er += __shfl_xor_sync(0xffffffffu, er, o);
        }
        if (lane == 0) {
            g_el[(long long)bh * NN + n0 + rb + r] = el * LOG2E;
            g_er[(long long)bh * NN + n0 + rb + r] = er * LOG2E;
        }
    }

#pragma unroll
    for (int r = 0; r < 16; r++) {
        unsigned tv;
        asm("cvt.rna.tf32.f32 %0, %1;" : "=r"(tv) : "f"(acc[r]));
        sT[c][rb + r] = __uint_as_float(tv);
    }
    __syncthreads();

    int jt  = n0 >> 7;
    int kc0 = (n0 >> 3) & 15;
#pragma unroll
    for (int k = 0; k < 4; k++) {
        int q = t + k * 256;
        int j4    = q & 1;
        int d_loc = (q >> 1) & 7;
        int nt    = (q >> 4) & 3;
        int kcl   = (q >> 6) & 3;
        int h2    = q >> 8;
        int dd   = nt * 8 + d_loc;
        int base = kcl * 8;
        int row  = h2 * 32 + dd;
        float4 v = make_float4(sT[row][base + 2 * j4],
                               sT[row][base + 2 * j4 + 4],
                               sT[row][base + 2 * j4 + 1],
                               sT[row][base + 2 * j4 + 5]);
        long long off = ((((long long)((b * HH + h2) * 16 + jt) * 16 + (kc0 + kcl)) * 4 + nt) * 64)
                        + d_loc * 8 + j4 * 4;
        *(float4*)(g_hB + off) = v;
    }
}

// ---------------------------------------------------------------------------
// Kernel C: masked-softmax + aggregate, j-split S=2.
// Block = 128 threads: (s, 64-i tile, hh, b). Warp = 16 i (one m16 tile) x
// the block's 1024-j range. No cross-warp reduction; NO reg cap (no spill).
// 1024 blocks -> 4096 warps (~28/SM resident).
// ---------------------------------------------------------------------------
__device__ __forceinline__ unsigned p_gen(float el, float er, unsigned wrd, int pos) {
    float e = el + er;
    float l = fmaxf(e, 0.2f * e);
    float pe;
    asm("ex2.approx.f32 %0, %1;" : "=f"(pe) : "f"(l));
    unsigned bit;
    asm("bfe.u32 %0, %1, %2, 1;" : "=r"(bit) : "r"(wrd), "r"(pos));
    float p = bit ? pe : 0.f;
    return __float_as_uint(p);
}

#define MMA4(accp, A0, A1, A2, A3, B0, B1)                                    \
    asm("mma.sync.aligned.m16n8k8.row.col.f32.tf32.tf32.f32 "                 \
        "{%0,%1,%2,%3}, {%4,%5,%6,%7}, {%8,%9}, {%0,%1,%2,%3};"               \
        : "+f"((accp)[0]), "+f"((accp)[1]), "+f"((accp)[2]), "+f"((accp)[3])  \
        : "r"(A0), "r"(A1), "r"(A2), "r"(A3), "r"(B0), "r"(B1))

__global__ __launch_bounds__(128) void gat_attn_mma_k() {
    __shared__ float er_s[1024];   // 4 KB: block's j-range
    __shared__ float Bf[4096];     // 16 KB: one 128-j fragment tile

    int t = threadIdx.x, w = t >> 5, lane = t & 31;
    int bid = blockIdx.x;
    int s  = bid & 1;
    int it = (bid >> 1) & 31;                // 32 i-tiles of 64
    int hh = (bid >> 6) & 3;
    int b  = bid >> 8;
    int bh = b * HH + hh;

    int iw = it * 64 + w * 16;
    int r  = lane >> 2;
    int c0 = lane & 3;

    {
        float4* edst = (float4*)er_s;
        const float4* esrc = (const float4*)(g_er + (long long)bh * NN + s * 1024);
        edst[t]       = esrc[t];
        edst[t + 128] = esrc[t + 128];
    }
    float el0 = g_el[(long long)bh * NN + iw + r];
    float el1 = g_el[(long long)bh * NN + iw + r + 8];

    float acc[4][4];
    float accS[4];
#pragma unroll
    for (int nt = 0; nt < 4; nt++)
#pragma unroll
        for (int q = 0; q < 4; q++) acc[nt][q] = 0.f;
#pragma unroll
    for (int q = 0; q < 4; q++) accS[q] = 0.f;

    const float* hBb = g_hB + (long long)bh * 65536;
    const unsigned* bitb = g_bits + (long long)b * 64 * NN;
    const unsigned ONE = 0x3F800000u;

    for (int mtl = 0; mtl < 8; mtl++) {
        int g = s * 8 + mtl;
        __syncthreads();
        {
            const float4* src = (const float4*)(hBb + g * 4096);
            float4* dst = (float4*)Bf;
#pragma unroll
            for (int k = 0; k < 8; k++) dst[t + k * 128] = src[t + k * 128];
        }
        const unsigned* bw = bitb + (long long)(g * 4 + c0) * NN + iw + r;
        unsigned w0a = bw[0], w0b = bw[8];
        __syncthreads();

#pragma unroll 4
        for (int kc = 0; kc < 16; kc++) {
            int eoff = mtl * 128 + kc * 8 + c0;
            float e0 = er_s[eoff];
            float e4 = er_s[eoff + 4];
            int p0 = 2 * kc, p1 = 2 * kc + 1;

            unsigned a0 = p_gen(el0, e0, w0a, p0);
            unsigned a1 = p_gen(el1, e0, w0b, p0);
            unsigned a2 = p_gen(el0, e4, w0a, p1);
            unsigned a3 = p_gen(el1, e4, w0b, p1);

            const float2* bp = (const float2*)(Bf + kc * 256) + lane;
#pragma unroll
            for (int nt = 0; nt < 4; nt++) {
                float2 bv = bp[nt * 32];
                MMA4(acc[nt], a0, a1, a2, a3,
                     __float_as_uint(bv.x), __float_as_uint(bv.y));
            }
            MMA4(accS, a0, a1, a2, a3, ONE, ONE);   // row sums
        }
    }

    // ---- write unnormalized partials (no cross-warp reduction needed) ----
    int sb = s * 16 + bh;
    int gi = iw + r;
    if (c0 == 0) {
        g_psum[(long long)sb * NN + gi]     = accS[0];
        g_psum[(long long)sb * NN + gi + 8] = accS[2];
    }
    float* pb = g_pacc + ((long long)sb * NN + gi) * DKK;
#pragma unroll
    for (int nt = 0; nt < 4; nt++) {
        int col = nt * 8 + 2 * c0;
        *(float2*)(pb + col)           = make_float2(acc[nt][0], acc[nt][1]);
        *(float2*)(pb + 8 * DKK + col) = make_float2(acc[nt][2], acc[nt][3]);
    }
}

// ---------------------------------------------------------------------------
// Kernel D: reduce the 2 j-split partials + normalize + write out.
// ---------------------------------------------------------------------------
__global__ __launch_bounds__(256) void reduce_k(float* __restrict__ out) {
    int q = blockIdx.x * 256 + threadIdx.x;   // 131072 threads
    int row  = q >> 2;
    int dseg = (q & 3) * 8;
    int bh = row >> 11;
    int i  = row & 2047;
    float s0 = g_psum[(long long)bh * NN + i];
    float s1 = g_psum[(long long)(16 + bh) * NN + i];
    float inv = 1.f / (s0 + s1);
    const float4* p0 = (const float4*)(g_pacc + ((long long)bh * NN + i) * DKK + dseg);
    const float4* p1 = (const float4*)(g_pacc + ((long long)(16 + bh) * NN + i) * DKK + dseg);
    float4* ob = (float4*)(out + ((long long)bh * NN + i) * DKK + dseg);
#pragma unroll
    for (int k = 0; k < 2; k++) {
        float4 u = p0[k], v = p1[k];
        ob[k] = make_float4((u.x + v.x) * inv, (u.y + v.y) * inv,
                            (u.z + v.z) * inv, (u.w + v.w) * inv);
    }
}

// ---------------------------------------------------------------------------
extern "C" void kernel_launch(void* const* d_in, const int* in_sizes, int n_in,
                              void* d_out, int out_size) {
    const float* x   = (const float*)d_in[0];
    const int*   adj = (const int*)d_in[1];
    const float* W   = (const float*)d_in[2];
    const float* a   = (const float*)d_in[3];
    float* out = (float*)d_out;

    pack_adj_k<<<512, 256>>>(adj);
    compute_h_k<<<(BB * NN) / 32, 256>>>(x, W, a);
    gat_attn_mma_k<<<BB * HH * 32 * 2, 128>>>();
    reduce_k<<<512, 256>>>(out);
}

// round 15
// speedup vs baseline: 1.1362x; 1.0640x over previous
#include <cuda_runtime.h>
#include <cstdint>

#define BB 4
#define NN 2048
#define FIN 128
#define HH 4
#define DKK 32
#define LOG2E 1.4426950408889634f

// Scratch (no cudaMalloc allowed)
__device__ float g_hB[BB*HH*16*16*4*64];   // tf32 H^T, MMA-B fragment order
__device__ float2 g_elx[BB*HH*NN];         // {exp2(el'), exp2(0.2 el')}
__device__ float2 g_erx[BB*HH*NN];         // {exp2(er'), exp2(0.2 er')}
__device__ unsigned g_bits[BB*64*NN];      // ballot-direct bitmask
__device__ float g_pacc[2*16*NN*DKK];      // j-split partial acc
__device__ float g_psum[2*16*NN];          // j-split partial row sums

__device__ __forceinline__ float ex2(float x) {
    float r;
    asm("ex2.approx.f32 %0, %1;" : "=f"(r) : "f"(x));
    return r;
}

// ---------------------------------------------------------------------------
// Kernel A: pack adj -> ballot-direct bitmask (word (b,g,s), bit (j>>2)&31).
// ---------------------------------------------------------------------------
__global__ __launch_bounds__(256) void pack_adj_k(const int* __restrict__ adj) {
    int t = threadIdx.x, w = t >> 5, lane = t & 31;
    int task = blockIdx.x * 8 + w;
    int ic = task & 63;
    int g  = (task >> 6) & 15;
    int b  = task >> 10;
    int i0 = ic * 32;
    const int4* src = (const int4*)(adj + ((long long)(b * NN + i0)) * NN + g * 128) + lane;
    unsigned m0 = 0, m1 = 0, m2 = 0, m3 = 0;
#pragma unroll 8
    for (int r = 0; r < 32; r++) {
        int4 v = src[(long long)r * (NN / 4)];
        unsigned b0 = __ballot_sync(0xffffffffu, v.x != 0);
        unsigned b1 = __ballot_sync(0xffffffffu, v.y != 0);
        unsigned b2 = __ballot_sync(0xffffffffu, v.z != 0);
        unsigned b3 = __ballot_sync(0xffffffffu, v.w != 0);
        if (lane == r) { m0 = b0; m1 = b1; m2 = b2; m3 = b3; }
    }
    unsigned* dst = g_bits + ((long long)(b * 16 + g) * 4) * NN + i0 + lane;
    dst[0]      = m0;
    dst[NN]     = m1;
    dst[2 * NN] = m2;
    dst[3 * NN] = m3;
}

// ---------------------------------------------------------------------------
// Kernel B: h = x @ W. Fragment-ordered tf32 g_hB + fused el/er (stored as
// precomputed exp2 pairs -> attention needs NO transcendentals).
// ---------------------------------------------------------------------------
__global__ __launch_bounds__(256) void compute_h_k(const float* __restrict__ x,
                                                   const float* __restrict__ W,
                                                   const float* __restrict__ a) {
    __shared__ float xs[32][FIN];
    __shared__ float sT[128][33];
    int t = threadIdx.x, lane = t & 31;
    int row0 = blockIdx.x * 32;
    for (int idx = t; idx < 32 * FIN; idx += 256)
        xs[idx >> 7][idx & 127] = x[(long long)row0 * FIN + idx];
    __syncthreads();

    int c  = t & 127;
    int hh = c >> 5;
    int d  = c & 31;
    int rb = (t >> 7) * 16;

    float acc[16];
#pragma unroll
    for (int r = 0; r < 16; r++) acc[r] = 0.f;

    const float* Wc = W + hh * FIN * DKK + d;
    for (int i0 = 0; i0 < FIN; i0 += 4) {
        float w0 = __ldg(Wc + i0 * DKK);
        float w1 = __ldg(Wc + (i0 + 1) * DKK);
        float w2 = __ldg(Wc + (i0 + 2) * DKK);
        float w3 = __ldg(Wc + (i0 + 3) * DKK);
#pragma unroll
        for (int r = 0; r < 16; r++) {
            float4 xv = *(const float4*)&xs[rb + r][i0];
            acc[r] = fmaf(xv.x, w0, acc[r]);
            acc[r] = fmaf(xv.y, w1, acc[r]);
            acc[r] = fmaf(xv.z, w2, acc[r]);
            acc[r] = fmaf(xv.w, w3, acc[r]);
        }
    }

    int b  = row0 / NN;
    int n0 = row0 % NN;
    int bh = b * HH + hh;

    float al = __ldg(a + hh * 2 * DKK + lane);
    float ar = __ldg(a + hh * 2 * DKK + DKK + lane);
#pragma unroll
    for (int r = 0; r < 16; r++) {
        float el = acc[r] * al, er = acc[r] * ar;
#pragma unroll
        for (int o = 16; o > 0; o >>= 1) {
            el += __shfl_xor_sync(0xffffffffu, el, o);
            er += __shfl_xor_sync(0xffffffffu, er, o);
        }
        if (lane == 0) {
            float elp = el * LOG2E, erp = er * LOG2E;
            g_elx[(long long)bh * NN + n0 + rb + r] =
                make_float2(ex2(elp), ex2(0.2f * elp));
            g_erx[(long long)bh * NN + n0 + rb + r] =
                make_float2(ex2(erp), ex2(0.2f * erp));
        }
    }

#pragma unroll
    for (int r = 0; r < 16; r++) {
        unsigned tv;
        asm("cvt.rna.tf32.f32 %0, %1;" : "=r"(tv) : "f"(acc[r]));
        sT[c][rb + r] = __uint_as_float(tv);
    }
    __syncthreads();

    int jt  = n0 >> 7;
    int kc0 = (n0 >> 3) & 15;
#pragma unroll
    for (int k = 0; k < 4; k++) {
        int q = t + k * 256;
        int j4    = q & 1;
        int d_loc = (q >> 1) & 7;
        int nt    = (q >> 4) & 3;
        int kcl   = (q >> 6) & 3;
        int h2    = q >> 8;
        int dd   = nt * 8 + d_loc;
        int base = kcl * 8;
        int row  = h2 * 32 + dd;
        float4 v = make_float4(sT[row][base + 2 * j4],
                               sT[row][base + 2 * j4 + 4],
                               sT[row][base + 2 * j4 + 1],
                               sT[row][base + 2 * j4 + 5]);
        long long off = ((((long long)((b * HH + h2) * 16 + jt) * 16 + (kc0 + kcl)) * 4 + nt) * 64)
                        + d_loc * 8 + j4 * 4;
        *(float4*)(g_hB + off) = v;
    }
}

// ---------------------------------------------------------------------------
// Kernel C: masked-softmax + aggregate, j-split S=2, NO transcendentals:
// P = adj ? max(Eel.x*Eer.x, Eel.y*Eer.y) : 0   (exp2 factorized + monotone
// max commutes with exp2). 5 issues per P. Warp = 16 i x 1024 j.
// ---------------------------------------------------------------------------
__device__ __forceinline__ unsigned p_gen(float2 El, float2 Er, unsigned wrd, int pos) {
    float p = fmaxf(El.x * Er.x, El.y * Er.y);
    unsigned bit;
    asm("bfe.u32 %0, %1, %2, 1;" : "=r"(bit) : "r"(wrd), "r"(pos));
    return __float_as_uint(bit ? p : 0.f);
}

#define MMA4(accp, A0, A1, A2, A3, B0, B1)                                    \
    asm("mma.sync.aligned.m16n8k8.row.col.f32.tf32.tf32.f32 "                 \
        "{%0,%1,%2,%3}, {%4,%5,%6,%7}, {%8,%9}, {%0,%1,%2,%3};"               \
        : "+f"((accp)[0]), "+f"((accp)[1]), "+f"((accp)[2]), "+f"((accp)[3])  \
        : "r"(A0), "r"(A1), "r"(A2), "r"(A3), "r"(B0), "r"(B1))

__global__ __launch_bounds__(128) void gat_attn_mma_k() {
    __shared__ float2 er_s[1024];  // 8 KB: block's j-range exp2 pairs
    __shared__ float Bf[4096];     // 16 KB: one 128-j fragment tile

    int t = threadIdx.x, w = t >> 5, lane = t & 31;
    int bid = blockIdx.x;
    int s  = bid & 1;
    int it = (bid >> 1) & 31;
    int hh = (bid >> 6) & 3;
    int b  = bid >> 8;
    int bh = b * HH + hh;

    int iw = it * 64 + w * 16;
    int r  = lane >> 2;
    int c0 = lane & 3;

    {
        float4* edst = (float4*)er_s;
        const float4* esrc = (const float4*)(g_erx + (long long)bh * NN + s * 1024);
#pragma unroll
        for (int k = 0; k < 4; k++) edst[t + k * 128] = esrc[t + k * 128];
    }
    float2 El0 = g_elx[(long long)bh * NN + iw + r];
    float2 El1 = g_elx[(long long)bh * NN + iw + r + 8];

    float acc[4][4];
    float accS[4];
#pragma unroll
    for (int nt = 0; nt < 4; nt++)
#pragma unroll
        for (int q = 0; q < 4; q++) acc[nt][q] = 0.f;
#pragma unroll
    for (int q = 0; q < 4; q++) accS[q] = 0.f;

    const float* hBb = g_hB + (long long)bh * 65536;
    const unsigned* bitb = g_bits + (long long)b * 64 * NN;
    const unsigned ONE = 0x3F800000u;

    for (int mtl = 0; mtl < 8; mtl++) {
        int g = s * 8 + mtl;
        __syncthreads();
        {
            const float4* src = (const float4*)(hBb + g * 4096);
            float4* dst = (float4*)Bf;
#pragma unroll
            for (int k = 0; k < 8; k++) dst[t + k * 128] = src[t + k * 128];
        }
        const unsigned* bw = bitb + (long long)(g * 4 + c0) * NN + iw + r;
        unsigned w0a = bw[0], w0b = bw[8];
        __syncthreads();

#pragma unroll 4
        for (int kc = 0; kc < 16; kc++) {
            int eoff = mtl * 128 + kc * 8 + c0;
            float2 e0 = er_s[eoff];
            float2 e4 = er_s[eoff + 4];
            int p0 = 2 * kc, p1 = 2 * kc + 1;

            unsigned a0 = p_gen(El0, e0, w0a, p0);
            unsigned a1 = p_gen(El1, e0, w0b, p0);
            unsigned a2 = p_gen(El0, e4, w0a, p1);
            unsigned a3 = p_gen(El1, e4, w0b, p1);

            const float2* bp = (const float2*)(Bf + kc * 256) + lane;
#pragma unroll
            for (int nt = 0; nt < 4; nt++) {
                float2 bv = bp[nt * 32];
                MMA4(acc[nt], a0, a1, a2, a3,
                     __float_as_uint(bv.x), __float_as_uint(bv.y));
            }
            MMA4(accS, a0, a1, a2, a3, ONE, ONE);   // row sums
        }
    }

    // ---- write unnormalized partials ----
    int sb = s * 16 + bh;
    int gi = iw + r;
    if (c0 == 0) {
        g_psum[(long long)sb * NN + gi]     = accS[0];
        g_psum[(long long)sb * NN + gi + 8] = accS[2];
    }
    float* pb = g_pacc + ((long long)sb * NN + gi) * DKK;
#pragma unroll
    for (int nt = 0; nt < 4; nt++) {
        int col = nt * 8 + 2 * c0;
        *(float2*)(pb + col)           = make_float2(acc[nt][0], acc[nt][1]);
        *(float2*)(pb + 8 * DKK + col) = make_float2(acc[nt][2], acc[nt][3]);
    }
}

// ---------------------------------------------------------------------------
// Kernel D: reduce the 2 j-split partials + normalize + write out.
// ---------------------------------------------------------------------------
__global__ __launch_bounds__(256) void reduce_k(float* __restrict__ out) {
    int q = blockIdx.x * 256 + threadIdx.x;   // 262144 threads
    int row  = q >> 3;                        // (bh, i)
    int dseg = (q & 7) * 4;
    int bh = row >> 11;
    int i  = row & 2047;
    float s0 = g_psum[(long long)bh * NN + i];
    float s1 = g_psum[(long long)(16 + bh) * NN + i];
    float inv = 1.f / (s0 + s1);
    float4 u = *(const float4*)(g_pacc + ((long long)bh * NN + i) * DKK + dseg);
    float4 v = *(const float4*)(g_pacc + ((long long)(16 + bh) * NN + i) * DKK + dseg);
    *(float4*)(out + ((long long)bh * NN + i) * DKK + dseg) =
        make_float4((u.x + v.x) * inv, (u.y + v.y) * inv,
                    (u.z + v.z) * inv, (u.w + v.w) * inv);
}

// ---------------------------------------------------------------------------
extern "C" void kernel_launch(void* const* d_in, const int* in_sizes, int n_in,
                              void* d_out, int out_size) {
    const float* x   = (const float*)d_in[0];
    const int*   adj = (const int*)d_in[1];
    const float* W   = (const float*)d_in[2];
    const float* a   = (const float*)d_in[3];
    float* out = (float*)d_out;

    pack_adj_k<<<512, 256>>>(adj);
    compute_h_k<<<(BB * NN) / 32, 256>>>(x, W, a);
    gat_attn_mma_k<<<BB * HH * 32 * 2, 128>>>();
    reduce_k<<<1024, 256>>>(out);
}